// round 1
// baseline (speedup 1.0000x reference)
#include <cuda_runtime.h>
#include <math.h>

// Problem dims (fixed by setup_inputs)
#define LSEQ 4096
#define DMODEL 256
#define DINNER 512
#define DSTATE 16
#define DTRANK 16
#define NDBC 48          // dt_rank + 2*d_state
#define NCHUNK 64
#define LC 64            // LSEQ / NCHUNK
#define HID 128
#define NC 7             // action dim C
#define NSTEP 3

// ---------------- scratch (static device memory; no allocations) ------------
__device__ float g_h[LSEQ * DMODEL];
__device__ float g_xz[LSEQ * 2 * DINNER];
__device__ float g_xc[LSEQ * DINNER];
__device__ float g_dbc[LSEQ * NDBC];
__device__ float g_delta[LSEQ * DINNER];
__device__ float g_Dpre[LSEQ * DINNER];
__device__ float g_y[LSEQ * DINNER];
__device__ float g_x2[LSEQ * DMODEL];
__device__ float g_feats[LSEQ * DMODEL];
__device__ float g_hf[LSEQ * HID];
__device__ float g_y0[LSEQ * NC];
__device__ float g_chunkS[NCHUNK * DINNER * DSTATE];
__device__ float g_chunkD[NCHUNK * DINNER];
__device__ float g_sinit[NCHUNK * DINNER * DSTATE];

// ---------------- helpers ---------------------------------------------------
__device__ __forceinline__ float softplus_f(float x) {
    return (x > 20.0f) ? x : log1pf(expf(x));
}
__device__ __forceinline__ float silu_f(float x) {
    return x / (1.0f + __expf(-x));
}
__device__ __forceinline__ float leaky_f(float x) {
    return (x >= 0.0f) ? x : 0.1f * x;
}

// ---------------- rmsnorm: one warp per row of 256 ---------------------------
__global__ void rmsnorm_kernel(const float* __restrict__ x,
                               const float* __restrict__ w,
                               float* __restrict__ out) {
    int wid = threadIdx.x >> 5, lane = threadIdx.x & 31;
    int row = blockIdx.x * 8 + wid;
    const float* xr = x + row * DMODEL;
    float ss = 0.0f;
    #pragma unroll
    for (int i = lane; i < DMODEL; i += 32) { float v = xr[i]; ss += v * v; }
    #pragma unroll
    for (int o = 16; o; o >>= 1) ss += __shfl_xor_sync(0xffffffffu, ss, o);
    float inv = rsqrtf(ss * (1.0f / DMODEL) + 1e-5f);
    #pragma unroll
    for (int i = lane; i < DMODEL; i += 32) out[row * DMODEL + i] = xr[i] * inv * w[i];
}

// ---------------- generic TN GEMM: C[M,N] = A[M,K] * B[N,K]^T + epilogue -----
// epi: 0 none | 1 +bias[n] | 2 softplus(x+bias[n]) | 3 +res[m*ldres+n]
__global__ void gemm_tn(const float* __restrict__ A, int lda,
                        const float* __restrict__ B, int ldb,
                        float* __restrict__ C, int ldc,
                        int M, int N, int K,
                        int epi, const float* __restrict__ bias,
                        const float* __restrict__ res, int ldres) {
    __shared__ float As[16][65];
    __shared__ float Bs[16][65];
    const int bm = blockIdx.y * 64, bn = blockIdx.x * 64;
    const int tid = threadIdx.x;
    const int tm = tid >> 4, tn = tid & 15;
    float acc[4][4] = {};

    for (int k0 = 0; k0 < K; k0 += 16) {
        int kk = tid & 15, mb = tid >> 4;
        #pragma unroll
        for (int p = 0; p < 4; p++) {
            int m = mb + p * 16;
            As[kk][m] = A[(size_t)(bm + m) * lda + k0 + kk];
            int n = mb + p * 16;
            Bs[kk][n] = (bn + n < N) ? B[(size_t)(bn + n) * ldb + k0 + kk] : 0.0f;
        }
        __syncthreads();
        #pragma unroll
        for (int k = 0; k < 16; k++) {
            float a[4], b[4];
            #pragma unroll
            for (int i = 0; i < 4; i++) a[i] = As[k][tm * 4 + i];
            #pragma unroll
            for (int j = 0; j < 4; j++) b[j] = Bs[k][tn * 4 + j];
            #pragma unroll
            for (int i = 0; i < 4; i++)
                #pragma unroll
                for (int j = 0; j < 4; j++) acc[i][j] += a[i] * b[j];
        }
        __syncthreads();
    }
    #pragma unroll
    for (int i = 0; i < 4; i++) {
        int row = bm + tm * 4 + i;
        #pragma unroll
        for (int j = 0; j < 4; j++) {
            int col = bn + tn * 4 + j;
            if (col < N) {
                float v = acc[i][j];
                if (epi == 1) v += bias[col];
                else if (epi == 2) v = softplus_f(v + bias[col]);
                else if (epi == 3) v += res[(size_t)row * ldres + col];
                C[(size_t)row * ldc + col] = v;
            }
        }
    }
}

// ---------------- causal depthwise conv (k=4) + silu -------------------------
__global__ void conv_silu_kernel(const float* __restrict__ cw,
                                 const float* __restrict__ cb) {
    int idx = blockIdx.x * blockDim.x + threadIdx.x;
    if (idx >= LSEQ * DINNER) return;
    int l = idx / DINNER, e = idx - l * DINNER;
    float acc = cb[e];
    #pragma unroll
    for (int k = 0; k < 4; k++) {
        int ls = l - 3 + k;
        if (ls >= 0) acc += cw[e * 4 + k] * g_xz[(size_t)ls * (2 * DINNER) + e];
    }
    g_xc[idx] = silu_f(acc);
}

// ---------------- scan pass 1: per-chunk zero-init local scan ----------------
__global__ void scan_pass1(const float* __restrict__ A_log) {
    int g = blockIdx.x, d = threadIdx.x;      // 64 blocks x 512 threads
    __shared__ float Bs[LC * DSTATE];
    __shared__ float Cs[LC * DSTATE];
    int l0 = g * LC;
    for (int i = d; i < LC * DSTATE; i += DINNER) {
        int l = i >> 4, n = i & 15;
        Bs[i] = g_dbc[(size_t)(l0 + l) * NDBC + DTRANK + n];
        Cs[i] = g_dbc[(size_t)(l0 + l) * NDBC + DTRANK + DSTATE + n];
    }
    __syncthreads();
    float An[DSTATE];
    #pragma unroll
    for (int n = 0; n < DSTATE; n++) An[n] = -expf(A_log[d * DSTATE + n]);
    float s[DSTATE];
    #pragma unroll
    for (int n = 0; n < DSTATE; n++) s[n] = 0.0f;
    float sumd = 0.0f;
    for (int l = 0; l < LC; l++) {
        size_t idx = (size_t)(l0 + l) * DINNER + d;
        float dlt = g_delta[idx];
        float xv  = g_xc[idx];
        float u = dlt * xv;
        sumd += dlt;
        float yl = 0.0f;
        #pragma unroll
        for (int n = 0; n < DSTATE; n++) {
            float dA = __expf(dlt * An[n]);
            s[n] = dA * s[n] + u * Bs[l * DSTATE + n];
            yl += s[n] * Cs[l * DSTATE + n];
        }
        g_y[idx] = yl;
        g_Dpre[idx] = sumd;
    }
    #pragma unroll
    for (int n = 0; n < DSTATE; n++)
        g_chunkS[((size_t)g * DINNER + d) * DSTATE + n] = s[n];
    g_chunkD[g * DINNER + d] = sumd;
}

// ---------------- scan combine: sequential over 64 chunks per (d,n) ----------
__global__ void scan_combine(const float* __restrict__ A_log) {
    int idx = blockIdx.x * blockDim.x + threadIdx.x;   // 8192 threads
    if (idx >= DINNER * DSTATE) return;
    int d = idx >> 4, n = idx & 15;
    float An = -expf(A_log[d * DSTATE + n]);
    float s = 0.0f;
    for (int g = 0; g < NCHUNK; g++) {
        g_sinit[((size_t)g * DINNER + d) * DSTATE + n] = s;
        s = __expf(An * g_chunkD[g * DINNER + d]) * s
            + g_chunkS[((size_t)g * DINNER + d) * DSTATE + n];
    }
}

// ---------------- scan pass 2: correction + gating epilogue ------------------
__global__ void scan_pass2(const float* __restrict__ A_log,
                           const float* __restrict__ Dp) {
    int g = blockIdx.x, d = threadIdx.x;
    __shared__ float Cs[LC * DSTATE];
    int l0 = g * LC;
    for (int i = d; i < LC * DSTATE; i += DINNER) {
        int l = i >> 4, n = i & 15;
        Cs[i] = g_dbc[(size_t)(l0 + l) * NDBC + DTRANK + DSTATE + n];
    }
    __syncthreads();
    float An[DSTATE], si[DSTATE];
    #pragma unroll
    for (int n = 0; n < DSTATE; n++) {
        An[n] = -expf(A_log[d * DSTATE + n]);
        si[n] = g_sinit[((size_t)g * DINNER + d) * DSTATE + n];
    }
    float dp = Dp[d];
    for (int l = 0; l < LC; l++) {
        size_t idx = (size_t)(l0 + l) * DINNER + d;
        float Dl = g_Dpre[idx];
        float corr = 0.0f;
        #pragma unroll
        for (int n = 0; n < DSTATE; n++)
            corr += __expf(Dl * An[n]) * si[n] * Cs[l * DSTATE + n];
        float yv = g_y[idx] + corr;
        float z = g_xz[(size_t)(l0 + l) * (2 * DINNER) + DINNER + d];
        yv = (yv + g_xc[idx] * dp) * silu_f(z);
        g_y[idx] = yv;
    }
}

// ---------------- softmax over C=7 ------------------------------------------
__global__ void softmax7(const float* __restrict__ logits) {
    int r = blockIdx.x * blockDim.x + threadIdx.x;
    if (r >= LSEQ) return;
    float v[NC], m = -1e30f;
    #pragma unroll
    for (int c = 0; c < NC; c++) { v[c] = logits[r * NC + c]; m = fmaxf(m, v[c]); }
    float s = 0.0f;
    #pragma unroll
    for (int c = 0; c < NC; c++) { v[c] = __expf(v[c] - m); s += v[c]; }
    float inv = 1.0f / s;
    #pragma unroll
    for (int c = 0; c < NC; c++) g_y0[r * NC + c] = v[c] * inv;
}

// ---------------- fused 3-step policy head: warp per row --------------------
#define POLICY_SMEM_FLOATS (128*129 + 128*7 + 128 + 128 + 7*128 + 7*128 + 8 + 8 + 8*128 + 8*8)
__global__ void policy_kernel(const float* __restrict__ fn1_W,
                              const float* __restrict__ fn1_b,
                              const float* __restrict__ fn2_W,
                              const float* __restrict__ fn2_b,
                              const float* __restrict__ muW,
                              const float* __restrict__ mub,
                              const float* __restrict__ varW,
                              const float* __restrict__ varb,
                              const float* __restrict__ eps,
                              float* __restrict__ out) {
    extern __shared__ float sm[];
    float* fn2s  = sm;                 // 128*129 (padded rows)
    float* Wys   = fn2s + 128 * 129;   // 128*7
    float* b1s   = Wys + 128 * 7;      // 128
    float* b2s   = b1s + 128;          // 128
    float* muWs  = b2s + 128;          // 7*128
    float* varWs = muWs + 7 * 128;     // 7*128
    float* mubs  = varWs + 7 * 128;    // 8
    float* varbs = mubs + 8;           // 8
    float* hbuf  = varbs + 8;          // 8*128
    float* ysh   = hbuf + 8 * 128;     // 8*8

    int tid = threadIdx.x, wid = tid >> 5, lane = tid & 31;
    for (int i = tid; i < 128 * 128; i += 256)
        fn2s[(i >> 7) * 129 + (i & 127)] = fn2_W[i];
    for (int i = tid; i < 128 * NC; i += 256) {
        int o = i / NC, c = i - o * NC;
        Wys[i] = fn1_W[o * (DMODEL + NC) + DMODEL + c];
    }
    for (int i = tid; i < 128; i += 256) { b1s[i] = fn1_b[i]; b2s[i] = fn2_b[i]; }
    for (int i = tid; i < NC * 128; i += 256) { muWs[i] = muW[i]; varWs[i] = varW[i]; }
    if (tid < NC) { mubs[tid] = mub[tid]; varbs[tid] = varb[tid]; }
    __syncthreads();

    int row = blockIdx.x * 8 + wid;
    float hfr[4];
    #pragma unroll
    for (int j = 0; j < 4; j++) {
        int o = lane + 32 * j;
        hfr[j] = g_hf[(size_t)row * HID + o] + b1s[o];
    }
    if (lane < NC) ysh[wid * 8 + lane] = g_y0[row * NC + lane];
    __syncwarp();

    for (int s = 0; s < NSTEP; s++) {
        float yv[NC];
        #pragma unroll
        for (int c = 0; c < NC; c++) yv[c] = ysh[wid * 8 + c];
        // h1 = leaky(hf + b1 + y * Wy^T)
        float h1[4];
        #pragma unroll
        for (int j = 0; j < 4; j++) {
            int o = lane + 32 * j;
            float a = hfr[j];
            #pragma unroll
            for (int c = 0; c < NC; c++) a += yv[c] * Wys[o * NC + c];
            h1[j] = leaky_f(a);
            hbuf[wid * 128 + o] = h1[j];
        }
        __syncwarp();
        // h2 = leaky(h1 @ fn2^T + b2)
        float h2[4];
        #pragma unroll
        for (int j = 0; j < 4; j++) {
            int o = lane + 32 * j;
            float a = b2s[o];
            #pragma unroll 8
            for (int i = 0; i < 128; i++) a += hbuf[wid * 128 + i] * fn2s[o * 129 + i];
            h2[j] = leaky_f(a);
        }
        // mu / var partials
        float pmu[NC], pvar[NC];
        #pragma unroll
        for (int c = 0; c < NC; c++) { pmu[c] = 0.0f; pvar[c] = 0.0f; }
        #pragma unroll
        for (int j = 0; j < 4; j++) {
            int o = lane + 32 * j;
            #pragma unroll
            for (int c = 0; c < NC; c++) {
                pmu[c]  += h2[j] * muWs[c * 128 + o];
                pvar[c] += h2[j] * varWs[c * 128 + o];
            }
        }
        #pragma unroll
        for (int off = 16; off; off >>= 1) {
            #pragma unroll
            for (int c = 0; c < NC; c++) {
                pmu[c]  += __shfl_xor_sync(0xffffffffu, pmu[c], off);
                pvar[c] += __shfl_xor_sync(0xffffffffu, pvar[c], off);
            }
        }
        __syncwarp();
        if (lane < NC) {
            float mu = pmu[lane] + mubs[lane];
            float var = softplus_f(pvar[lane] + varbs[lane]);
            float e = eps[((size_t)s * LSEQ + row) * NC + lane];
            float ynew = ysh[wid * 8 + lane] - (mu + var * e);
            ysh[wid * 8 + lane] = ynew;
            out[((size_t)s * LSEQ + row) * NC + lane] = ynew;
        }
        __syncwarp();
    }
}

// ---------------- launch ------------------------------------------------------
extern "C" void kernel_launch(void* const* d_in, const int* in_sizes, int n_in,
                              void* d_out, int out_size) {
    const float* features  = (const float*)d_in[0];
    const float* y_init    = (const float*)d_in[1];
    const float* eps       = (const float*)d_in[2];
    const float* in_proj_W = (const float*)d_in[3];
    const float* conv_W    = (const float*)d_in[4];
    const float* conv_b    = (const float*)d_in[5];
    const float* x_proj_W  = (const float*)d_in[6];
    const float* dt_proj_W = (const float*)d_in[7];
    const float* dt_proj_b = (const float*)d_in[8];
    const float* A_log     = (const float*)d_in[9];
    const float* Dp        = (const float*)d_in[10];
    const float* out_proj_W= (const float*)d_in[11];
    const float* norm_w    = (const float*)d_in[12];
    const float* norm_f_w  = (const float*)d_in[13];
    const float* lm_head_W = (const float*)d_in[14];
    const float* fn1_W     = (const float*)d_in[15];
    const float* fn1_b     = (const float*)d_in[16];
    const float* fn2_W     = (const float*)d_in[17];
    const float* fn2_b     = (const float*)d_in[18];
    const float* mu_W      = (const float*)d_in[19];
    const float* mu_b      = (const float*)d_in[20];
    const float* var_W     = (const float*)d_in[21];
    const float* var_b     = (const float*)d_in[22];
    float* out = (float*)d_out;

    float *ph, *pxz, *pxc, *pdbc, *pdelta, *py, *px2, *pfeats, *phf;
    cudaGetSymbolAddress((void**)&ph, g_h);
    cudaGetSymbolAddress((void**)&pxz, g_xz);
    cudaGetSymbolAddress((void**)&pxc, g_xc);
    cudaGetSymbolAddress((void**)&pdbc, g_dbc);
    cudaGetSymbolAddress((void**)&pdelta, g_delta);
    cudaGetSymbolAddress((void**)&py, g_y);
    cudaGetSymbolAddress((void**)&px2, g_x2);
    cudaGetSymbolAddress((void**)&pfeats, g_feats);
    cudaGetSymbolAddress((void**)&phf, g_hf);

    // 1) rmsnorm(features)
    rmsnorm_kernel<<<LSEQ / 8, 256>>>(features, norm_w, ph);
    // 2) in_proj: (4096,256)x(1024,256)^T
    gemm_tn<<<dim3((2 * DINNER) / 64, LSEQ / 64), 256>>>(
        ph, DMODEL, in_proj_W, DMODEL, pxz, 2 * DINNER,
        LSEQ, 2 * DINNER, DMODEL, 0, nullptr, nullptr, 0);
    // 3) conv + silu
    conv_silu_kernel<<<(LSEQ * DINNER + 255) / 256, 256>>>(conv_W, conv_b);
    // 4) x_proj: (4096,512)x(48,512)^T
    gemm_tn<<<dim3(1, LSEQ / 64), 256>>>(
        pxc, DINNER, x_proj_W, DINNER, pdbc, NDBC,
        LSEQ, NDBC, DINNER, 0, nullptr, nullptr, 0);
    // 5) dt_proj + softplus: (4096,16)x(512,16)^T
    gemm_tn<<<dim3(DINNER / 64, LSEQ / 64), 256>>>(
        pdbc, NDBC, dt_proj_W, DTRANK, pdelta, DINNER,
        LSEQ, DINNER, DTRANK, 2, dt_proj_b, nullptr, 0);
    // 6-8) chunked selective scan
    scan_pass1<<<NCHUNK, DINNER>>>(A_log);
    scan_combine<<<(DINNER * DSTATE) / 256, 256>>>(A_log);
    scan_pass2<<<NCHUNK, DINNER>>>(A_log, Dp);
    // 9) out_proj + residual: (4096,512)x(256,512)^T + features
    gemm_tn<<<dim3(DMODEL / 64, LSEQ / 64), 256>>>(
        py, DINNER, out_proj_W, DINNER, px2, DMODEL,
        LSEQ, DMODEL, DINNER, 3, nullptr, features, DMODEL);
    // 10) final rmsnorm
    rmsnorm_kernel<<<LSEQ / 8, 256>>>(px2, norm_f_w, ph);
    // 11) lm_head
    gemm_tn<<<dim3(DMODEL / 64, LSEQ / 64), 256>>>(
        ph, DMODEL, lm_head_W, DMODEL, pfeats, DMODEL,
        LSEQ, DMODEL, DMODEL, 0, nullptr, nullptr, 0);
    // 12) hf = feats @ fn1_W[:, :256]^T  (ldb = 263)
    gemm_tn<<<dim3(HID / 64, LSEQ / 64), 256>>>(
        pfeats, DMODEL, fn1_W, DMODEL + NC, phf, HID,
        LSEQ, HID, DMODEL, 0, nullptr, nullptr, 0);
    // 13) softmax init
    softmax7<<<(LSEQ + 255) / 256, 256>>>(y_init);
    // 14) fused policy loop
    int smemP = POLICY_SMEM_FLOATS * (int)sizeof(float);
    cudaFuncSetAttribute(policy_kernel,
                         cudaFuncAttributeMaxDynamicSharedMemorySize, smemP);
    policy_kernel<<<LSEQ / 8, 256, smemP>>>(fn1_W, fn1_b, fn2_W, fn2_b,
                                            mu_W, mu_b, var_W, var_b, eps, out);
}

// round 2
// speedup vs baseline: 1.7931x; 1.7931x over previous
#include <cuda_runtime.h>
#include <math.h>

// Problem dims (fixed by setup_inputs)
#define LSEQ 4096
#define DMODEL 256
#define DINNER 512
#define DSTATE 16
#define DTRANK 16
#define NDBC 48          // dt_rank + 2*d_state
#define NCHUNK 64
#define LC 64            // LSEQ / NCHUNK
#define HID 128
#define NC 7             // action dim C
#define NSTEP 3
#define XSPLIT 4

// ---------------- scratch (static device memory; no allocations) ------------
__device__ float g_h[LSEQ * DMODEL];
__device__ float g_xz[LSEQ * 2 * DINNER];
__device__ float g_xc[LSEQ * DINNER];
__device__ float g_dbc[LSEQ * NDBC];
__device__ float g_dbc_part[XSPLIT * LSEQ * NDBC];
__device__ float g_delta[LSEQ * DINNER];
__device__ float g_Dpre[LSEQ * DINNER];
__device__ float g_y[LSEQ * DINNER];
__device__ float g_x2[LSEQ * DMODEL];
__device__ float g_feats[LSEQ * DMODEL];
__device__ float g_hf[LSEQ * HID];
__device__ float g_y0[LSEQ * NC];
__device__ float g_fn1p[HID * DMODEL];
__device__ float g_chunkS[NCHUNK * DINNER * DSTATE];
__device__ float g_chunkD[NCHUNK * DINNER];
__device__ float g_sinit[NCHUNK * DINNER * DSTATE];

// ---------------- helpers ---------------------------------------------------
__device__ __forceinline__ float softplus_f(float x) {
    return (x > 20.0f) ? x : log1pf(expf(x));
}
__device__ __forceinline__ float silu_f(float x) {
    return x / (1.0f + __expf(-x));
}
__device__ __forceinline__ float leaky_f(float x) {
    return (x >= 0.0f) ? x : 0.1f * x;
}

// ---------------- rmsnorm: one warp per row of 256 ---------------------------
__global__ void rmsnorm_kernel(const float* __restrict__ x,
                               const float* __restrict__ w,
                               float* __restrict__ out) {
    int wid = threadIdx.x >> 5, lane = threadIdx.x & 31;
    int row = blockIdx.x * 8 + wid;
    const float* xr = x + row * DMODEL;
    float ss = 0.0f;
    #pragma unroll
    for (int i = lane; i < DMODEL; i += 32) { float v = xr[i]; ss += v * v; }
    #pragma unroll
    for (int o = 16; o; o >>= 1) ss += __shfl_xor_sync(0xffffffffu, ss, o);
    float inv = rsqrtf(ss * (1.0f / DMODEL) + 1e-5f);
    #pragma unroll
    for (int i = lane; i < DMODEL; i += 32) out[row * DMODEL + i] = xr[i] * inv * w[i];
}

// ---------------- GEMM v2: C[M,N] = A[M,K] * B[N,K]^T ------------------------
// 64x64 tile, K-step 32, float4 global loads, shared stored [k][m] / [k][n].
// epi: 0 none | 1 +bias | 2 softplus(+bias) | 3 +res
// Split-K: gridDim.z splits; block z handles k in [z*Klen, z*Klen+Klen),
// writing to C + z*M*ldc (epi must be 0 for split mode).
__global__ void gemm_v2(const float* __restrict__ A, int lda,
                        const float* __restrict__ B, int ldb,
                        float* __restrict__ C, int ldc,
                        int M, int N, int Klen,
                        int epi, const float* __restrict__ bias,
                        const float* __restrict__ res, int ldres) {
    __shared__ float As[32 * 64];
    __shared__ float Bs[32 * 64];
    const int bm = blockIdx.y * 64, bn = blockIdx.x * 64;
    const int kbase = blockIdx.z * Klen;
    const int kend = kbase + Klen;
    if (gridDim.z > 1) C += (size_t)blockIdx.z * M * ldc;
    const int tid = threadIdx.x;
    const int tm = tid >> 4, tn = tid & 15;
    float4* As4 = (float4*)As;
    float4* Bs4 = (float4*)Bs;
    float acc[4][4] = {};

    for (int k0 = kbase; k0 < kend; k0 += 32) {
        #pragma unroll
        for (int p = 0; p < 2; p++) {
            int idx = tid + p * 256;
            int r = idx & 63;           // row within tile (consecutive per lane)
            int k4 = idx >> 6;          // 0..7, float4 index along k
            int kg = k0 + k4 * 4;
            float4 av = make_float4(0.f, 0.f, 0.f, 0.f);
            float4 bv = make_float4(0.f, 0.f, 0.f, 0.f);
            if (kg < kend) {
                av = *(const float4*)&A[(size_t)(bm + r) * lda + kg];
                if (bn + r < N)
                    bv = *(const float4*)&B[(size_t)(bn + r) * ldb + kg];
            }
            int kl = k4 * 4;
            As[(kl + 0) * 64 + r] = av.x;
            As[(kl + 1) * 64 + r] = av.y;
            As[(kl + 2) * 64 + r] = av.z;
            As[(kl + 3) * 64 + r] = av.w;
            Bs[(kl + 0) * 64 + r] = bv.x;
            Bs[(kl + 1) * 64 + r] = bv.y;
            Bs[(kl + 2) * 64 + r] = bv.z;
            Bs[(kl + 3) * 64 + r] = bv.w;
        }
        __syncthreads();
        #pragma unroll
        for (int k = 0; k < 32; k++) {
            float4 a4 = As4[k * 16 + tm];
            float4 b4 = Bs4[k * 16 + tn];
            acc[0][0] += a4.x * b4.x; acc[0][1] += a4.x * b4.y;
            acc[0][2] += a4.x * b4.z; acc[0][3] += a4.x * b4.w;
            acc[1][0] += a4.y * b4.x; acc[1][1] += a4.y * b4.y;
            acc[1][2] += a4.y * b4.z; acc[1][3] += a4.y * b4.w;
            acc[2][0] += a4.z * b4.x; acc[2][1] += a4.z * b4.y;
            acc[2][2] += a4.z * b4.z; acc[2][3] += a4.z * b4.w;
            acc[3][0] += a4.w * b4.x; acc[3][1] += a4.w * b4.y;
            acc[3][2] += a4.w * b4.z; acc[3][3] += a4.w * b4.w;
        }
        __syncthreads();
    }
    #pragma unroll
    for (int i = 0; i < 4; i++) {
        int row = bm + tm * 4 + i;
        int colb = bn + tn * 4;
        if (colb < N) {   // N is a multiple of 4; whole float4 valid or not
            float4 v = make_float4(acc[i][0], acc[i][1], acc[i][2], acc[i][3]);
            if (epi == 1) {
                v.x += bias[colb]; v.y += bias[colb + 1];
                v.z += bias[colb + 2]; v.w += bias[colb + 3];
            } else if (epi == 2) {
                v.x = softplus_f(v.x + bias[colb]);
                v.y = softplus_f(v.y + bias[colb + 1]);
                v.z = softplus_f(v.z + bias[colb + 2]);
                v.w = softplus_f(v.w + bias[colb + 3]);
            } else if (epi == 3) {
                float4 r4 = *(const float4*)&res[(size_t)row * ldres + colb];
                v.x += r4.x; v.y += r4.y; v.z += r4.z; v.w += r4.w;
            }
            *(float4*)&C[(size_t)row * ldc + colb] = v;
        }
    }
}

// ---------------- reduce split-K partials for x_proj -------------------------
__global__ void reduce_xproj() {
    int i = blockIdx.x * blockDim.x + threadIdx.x;
    if (i >= LSEQ * NDBC) return;
    float s = g_dbc_part[i];
    #pragma unroll
    for (int z = 1; z < XSPLIT; z++) s += g_dbc_part[z * LSEQ * NDBC + i];
    g_dbc[i] = s;
}

// ---------------- pack fn1_W[:, :256] into ldb=256 ---------------------------
__global__ void pack_fn1(const float* __restrict__ fn1_W) {
    int i = blockIdx.x * blockDim.x + threadIdx.x;
    if (i >= HID * DMODEL) return;
    int o = i >> 8, d = i & 255;
    g_fn1p[i] = fn1_W[o * (DMODEL + NC) + d];
}

// ---------------- causal depthwise conv (k=4) + silu -------------------------
__global__ void conv_silu_kernel(const float* __restrict__ cw,
                                 const float* __restrict__ cb) {
    int idx = blockIdx.x * blockDim.x + threadIdx.x;
    if (idx >= LSEQ * DINNER) return;
    int l = idx / DINNER, e = idx - l * DINNER;
    float acc = cb[e];
    #pragma unroll
    for (int k = 0; k < 4; k++) {
        int ls = l - 3 + k;
        if (ls >= 0) acc += cw[e * 4 + k] * g_xz[(size_t)ls * (2 * DINNER) + e];
    }
    g_xc[idx] = silu_f(acc);
}

// ---------------- scan pass 1: per-chunk zero-init local scan ----------------
__global__ void scan_pass1(const float* __restrict__ A_log) {
    int g = blockIdx.x, d = threadIdx.x;      // 64 blocks x 512 threads
    __shared__ float Bs[LC * DSTATE];
    __shared__ float Cs[LC * DSTATE];
    int l0 = g * LC;
    for (int i = d; i < LC * DSTATE; i += DINNER) {
        int l = i >> 4, n = i & 15;
        Bs[i] = g_dbc[(size_t)(l0 + l) * NDBC + DTRANK + n];
        Cs[i] = g_dbc[(size_t)(l0 + l) * NDBC + DTRANK + DSTATE + n];
    }
    __syncthreads();
    float An[DSTATE];
    #pragma unroll
    for (int n = 0; n < DSTATE; n++) An[n] = -expf(A_log[d * DSTATE + n]);
    float s[DSTATE];
    #pragma unroll
    for (int n = 0; n < DSTATE; n++) s[n] = 0.0f;
    float sumd = 0.0f;
    for (int l = 0; l < LC; l++) {
        size_t idx = (size_t)(l0 + l) * DINNER + d;
        float dlt = g_delta[idx];
        float xv  = g_xc[idx];
        float u = dlt * xv;
        sumd += dlt;
        float yl = 0.0f;
        #pragma unroll
        for (int n = 0; n < DSTATE; n++) {
            float dA = __expf(dlt * An[n]);
            s[n] = dA * s[n] + u * Bs[l * DSTATE + n];
            yl += s[n] * Cs[l * DSTATE + n];
        }
        g_y[idx] = yl;
        g_Dpre[idx] = sumd;
    }
    #pragma unroll
    for (int n = 0; n < DSTATE; n++)
        g_chunkS[((size_t)g * DINNER + d) * DSTATE + n] = s[n];
    g_chunkD[g * DINNER + d] = sumd;
}

// ---------------- scan combine: sequential over 64 chunks per (d,n) ----------
__global__ void scan_combine(const float* __restrict__ A_log) {
    int idx = blockIdx.x * blockDim.x + threadIdx.x;   // 8192 threads
    if (idx >= DINNER * DSTATE) return;
    int d = idx >> 4, n = idx & 15;
    float An = -expf(A_log[d * DSTATE + n]);
    float s = 0.0f;
    for (int g = 0; g < NCHUNK; g++) {
        g_sinit[((size_t)g * DINNER + d) * DSTATE + n] = s;
        s = __expf(An * g_chunkD[g * DINNER + d]) * s
            + g_chunkS[((size_t)g * DINNER + d) * DSTATE + n];
    }
}

// ---------------- scan pass 2: correction + gating epilogue ------------------
__global__ void scan_pass2(const float* __restrict__ A_log,
                           const float* __restrict__ Dp) {
    int g = blockIdx.x, d = threadIdx.x;
    __shared__ float Cs[LC * DSTATE];
    int l0 = g * LC;
    for (int i = d; i < LC * DSTATE; i += DINNER) {
        int l = i >> 4, n = i & 15;
        Cs[i] = g_dbc[(size_t)(l0 + l) * NDBC + DTRANK + DSTATE + n];
    }
    __syncthreads();
    float An[DSTATE], si[DSTATE];
    #pragma unroll
    for (int n = 0; n < DSTATE; n++) {
        An[n] = -expf(A_log[d * DSTATE + n]);
        si[n] = g_sinit[((size_t)g * DINNER + d) * DSTATE + n];
    }
    float dp = Dp[d];
    for (int l = 0; l < LC; l++) {
        size_t idx = (size_t)(l0 + l) * DINNER + d;
        float Dl = g_Dpre[idx];
        float corr = 0.0f;
        #pragma unroll
        for (int n = 0; n < DSTATE; n++)
            corr += __expf(Dl * An[n]) * si[n] * Cs[l * DSTATE + n];
        float yv = g_y[idx] + corr;
        float z = g_xz[(size_t)(l0 + l) * (2 * DINNER) + DINNER + d];
        yv = (yv + g_xc[idx] * dp) * silu_f(z);
        g_y[idx] = yv;
    }
}

// ---------------- softmax over C=7 ------------------------------------------
__global__ void softmax7(const float* __restrict__ logits) {
    int r = blockIdx.x * blockDim.x + threadIdx.x;
    if (r >= LSEQ) return;
    float v[NC], m = -1e30f;
    #pragma unroll
    for (int c = 0; c < NC; c++) { v[c] = logits[r * NC + c]; m = fmaxf(m, v[c]); }
    float s = 0.0f;
    #pragma unroll
    for (int c = 0; c < NC; c++) { v[c] = __expf(v[c] - m); s += v[c]; }
    float inv = 1.0f / s;
    #pragma unroll
    for (int c = 0; c < NC; c++) g_y0[r * NC + c] = v[c] * inv;
}

// ---------------- fused 3-step policy head: warp per row --------------------
#define POLICY_SMEM_FLOATS (128*132 + 128*7 + 128 + 128 + 7*128 + 7*128 + 8 + 8 + 8*128 + 8*8)
__global__ void policy_kernel(const float* __restrict__ fn1_W,
                              const float* __restrict__ fn1_b,
                              const float* __restrict__ fn2_W,
                              const float* __restrict__ fn2_b,
                              const float* __restrict__ muW,
                              const float* __restrict__ mub,
                              const float* __restrict__ varW,
                              const float* __restrict__ varb,
                              const float* __restrict__ eps,
                              float* __restrict__ out) {
    extern __shared__ float sm[];
    float* fn2s  = sm;                 // 128*132 (padded rows, float4-aligned)
    float* Wys   = fn2s + 128 * 132;   // 128*7
    float* b1s   = Wys + 128 * 7;      // 128
    float* b2s   = b1s + 128;          // 128
    float* muWs  = b2s + 128;          // 7*128
    float* varWs = muWs + 7 * 128;     // 7*128
    float* mubs  = varWs + 7 * 128;    // 8
    float* varbs = mubs + 8;           // 8
    float* hbuf  = varbs + 8;          // 8*128
    float* ysh   = hbuf + 8 * 128;     // 8*8

    int tid = threadIdx.x, wid = tid >> 5, lane = tid & 31;
    for (int i = tid; i < 128 * 128; i += 256)
        fn2s[(i >> 7) * 132 + (i & 127)] = fn2_W[i];
    for (int i = tid; i < 128 * NC; i += 256) {
        int o = i / NC, c = i - o * NC;
        Wys[i] = fn1_W[o * (DMODEL + NC) + DMODEL + c];
    }
    for (int i = tid; i < 128; i += 256) { b1s[i] = fn1_b[i]; b2s[i] = fn2_b[i]; }
    for (int i = tid; i < NC * 128; i += 256) { muWs[i] = muW[i]; varWs[i] = varW[i]; }
    if (tid < NC) { mubs[tid] = mub[tid]; varbs[tid] = varb[tid]; }
    __syncthreads();

    int row = blockIdx.x * 8 + wid;
    float hfr[4];
    #pragma unroll
    for (int j = 0; j < 4; j++) {
        int o = lane + 32 * j;
        hfr[j] = g_hf[(size_t)row * HID + o] + b1s[o];
    }
    if (lane < NC) ysh[wid * 8 + lane] = g_y0[row * NC + lane];
    __syncwarp();

    float4* hb4 = (float4*)(hbuf + wid * 128);

    for (int s = 0; s < NSTEP; s++) {
        float yv[NC];
        #pragma unroll
        for (int c = 0; c < NC; c++) yv[c] = ysh[wid * 8 + c];
        // h1 = leaky(hf + b1 + y * Wy^T)
        #pragma unroll
        for (int j = 0; j < 4; j++) {
            int o = lane + 32 * j;
            float a = hfr[j];
            #pragma unroll
            for (int c = 0; c < NC; c++) a += yv[c] * Wys[o * NC + c];
            hbuf[wid * 128 + o] = leaky_f(a);
        }
        __syncwarp();
        // h2 = leaky(h1 @ fn2^T + b2) — float4 over shared
        int o0 = lane, o1 = lane + 32, o2 = lane + 64, o3 = lane + 96;
        float a0 = b2s[o0], a1 = b2s[o1], a2 = b2s[o2], a3 = b2s[o3];
        const float4* f0 = (const float4*)(fn2s + o0 * 132);
        const float4* f1 = (const float4*)(fn2s + o1 * 132);
        const float4* f2 = (const float4*)(fn2s + o2 * 132);
        const float4* f3 = (const float4*)(fn2s + o3 * 132);
        #pragma unroll 8
        for (int i4 = 0; i4 < 32; i4++) {
            float4 h4 = hb4[i4];
            float4 w0 = f0[i4], w1 = f1[i4], w2 = f2[i4], w3 = f3[i4];
            a0 += h4.x * w0.x + h4.y * w0.y + h4.z * w0.z + h4.w * w0.w;
            a1 += h4.x * w1.x + h4.y * w1.y + h4.z * w1.z + h4.w * w1.w;
            a2 += h4.x * w2.x + h4.y * w2.y + h4.z * w2.z + h4.w * w2.w;
            a3 += h4.x * w3.x + h4.y * w3.y + h4.z * w3.z + h4.w * w3.w;
        }
        float h2[4] = { leaky_f(a0), leaky_f(a1), leaky_f(a2), leaky_f(a3) };
        // mu / var partials
        float pmu[NC], pvar[NC];
        #pragma unroll
        for (int c = 0; c < NC; c++) { pmu[c] = 0.0f; pvar[c] = 0.0f; }
        #pragma unroll
        for (int j = 0; j < 4; j++) {
            int o = lane + 32 * j;
            #pragma unroll
            for (int c = 0; c < NC; c++) {
                pmu[c]  += h2[j] * muWs[c * 128 + o];
                pvar[c] += h2[j] * varWs[c * 128 + o];
            }
        }
        #pragma unroll
        for (int off = 16; off; off >>= 1) {
            #pragma unroll
            for (int c = 0; c < NC; c++) {
                pmu[c]  += __shfl_xor_sync(0xffffffffu, pmu[c], off);
                pvar[c] += __shfl_xor_sync(0xffffffffu, pvar[c], off);
            }
        }
        __syncwarp();
        if (lane < NC) {
            float mu = pmu[lane] + mubs[lane];
            float var = softplus_f(pvar[lane] + varbs[lane]);
            float e = eps[((size_t)s * LSEQ + row) * NC + lane];
            float ynew = ysh[wid * 8 + lane] - (mu + var * e);
            ysh[wid * 8 + lane] = ynew;
            out[((size_t)s * LSEQ + row) * NC + lane] = ynew;
        }
        __syncwarp();
    }
}

// ---------------- launch ------------------------------------------------------
extern "C" void kernel_launch(void* const* d_in, const int* in_sizes, int n_in,
                              void* d_out, int out_size) {
    const float* features  = (const float*)d_in[0];
    const float* y_init    = (const float*)d_in[1];
    const float* eps       = (const float*)d_in[2];
    const float* in_proj_W = (const float*)d_in[3];
    const float* conv_W    = (const float*)d_in[4];
    const float* conv_b    = (const float*)d_in[5];
    const float* x_proj_W  = (const float*)d_in[6];
    const float* dt_proj_W = (const float*)d_in[7];
    const float* dt_proj_b = (const float*)d_in[8];
    const float* A_log     = (const float*)d_in[9];
    const float* Dp        = (const float*)d_in[10];
    const float* out_proj_W= (const float*)d_in[11];
    const float* norm_w    = (const float*)d_in[12];
    const float* norm_f_w  = (const float*)d_in[13];
    const float* lm_head_W = (const float*)d_in[14];
    const float* fn1_W     = (const float*)d_in[15];
    const float* fn1_b     = (const float*)d_in[16];
    const float* fn2_W     = (const float*)d_in[17];
    const float* fn2_b     = (const float*)d_in[18];
    const float* mu_W      = (const float*)d_in[19];
    const float* mu_b      = (const float*)d_in[20];
    const float* var_W     = (const float*)d_in[21];
    const float* var_b     = (const float*)d_in[22];
    float* out = (float*)d_out;

    float *ph, *pxz, *pxc, *pdbc, *pdbcp, *pdelta, *py, *px2, *pfeats, *phf, *pfn1p;
    cudaGetSymbolAddress((void**)&ph, g_h);
    cudaGetSymbolAddress((void**)&pxz, g_xz);
    cudaGetSymbolAddress((void**)&pxc, g_xc);
    cudaGetSymbolAddress((void**)&pdbc, g_dbc);
    cudaGetSymbolAddress((void**)&pdbcp, g_dbc_part);
    cudaGetSymbolAddress((void**)&pdelta, g_delta);
    cudaGetSymbolAddress((void**)&py, g_y);
    cudaGetSymbolAddress((void**)&px2, g_x2);
    cudaGetSymbolAddress((void**)&pfeats, g_feats);
    cudaGetSymbolAddress((void**)&phf, g_hf);
    cudaGetSymbolAddress((void**)&pfn1p, g_fn1p);

    // pack fn1 (needed only before hf GEMM)
    pack_fn1<<<(HID * DMODEL + 255) / 256, 256>>>(fn1_W);
    // 1) rmsnorm(features)
    rmsnorm_kernel<<<LSEQ / 8, 256>>>(features, norm_w, ph);
    // 2) in_proj: (4096,256)x(1024,256)^T
    gemm_v2<<<dim3((2 * DINNER) / 64, LSEQ / 64), 256>>>(
        ph, DMODEL, in_proj_W, DMODEL, pxz, 2 * DINNER,
        LSEQ, 2 * DINNER, DMODEL, 0, nullptr, nullptr, 0);
    // 3) conv + silu
    conv_silu_kernel<<<(LSEQ * DINNER + 255) / 256, 256>>>(conv_W, conv_b);
    // 4) x_proj split-K: (4096,512)x(48,512)^T, 4 K-splits
    gemm_v2<<<dim3(1, LSEQ / 64, XSPLIT), 256>>>(
        pxc, DINNER, x_proj_W, DINNER, pdbcp, NDBC,
        LSEQ, NDBC, DINNER / XSPLIT, 0, nullptr, nullptr, 0);
    reduce_xproj<<<(LSEQ * NDBC + 255) / 256, 256>>>();
    // 5) dt_proj + softplus: (4096,16)x(512,16)^T
    gemm_v2<<<dim3(DINNER / 64, LSEQ / 64), 256>>>(
        pdbc, NDBC, dt_proj_W, DTRANK, pdelta, DINNER,
        LSEQ, DINNER, DTRANK, 2, dt_proj_b, nullptr, 0);
    // 6-8) chunked selective scan
    scan_pass1<<<NCHUNK, DINNER>>>(A_log);
    scan_combine<<<(DINNER * DSTATE) / 256, 256>>>(A_log);
    scan_pass2<<<NCHUNK, DINNER>>>(A_log, Dp);
    // 9) out_proj + residual: (4096,512)x(256,512)^T + features
    gemm_v2<<<dim3(DMODEL / 64, LSEQ / 64), 256>>>(
        py, DINNER, out_proj_W, DINNER, px2, DMODEL,
        LSEQ, DMODEL, DINNER, 3, nullptr, features, DMODEL);
    // 10) final rmsnorm
    rmsnorm_kernel<<<LSEQ / 8, 256>>>(px2, norm_f_w, ph);
    // 11) lm_head
    gemm_v2<<<dim3(DMODEL / 64, LSEQ / 64), 256>>>(
        ph, DMODEL, lm_head_W, DMODEL, pfeats, DMODEL,
        LSEQ, DMODEL, DMODEL, 0, nullptr, nullptr, 0);
    // 12) hf = feats @ fn1p^T  (packed ldb=256)
    gemm_v2<<<dim3(HID / 64, LSEQ / 64), 256>>>(
        pfeats, DMODEL, pfn1p, DMODEL, phf, HID,
        LSEQ, HID, DMODEL, 0, nullptr, nullptr, 0);
    // 13) softmax init
    softmax7<<<(LSEQ + 255) / 256, 256>>>(y_init);
    // 14) fused policy loop
    int smemP = POLICY_SMEM_FLOATS * (int)sizeof(float);
    cudaFuncSetAttribute(policy_kernel,
                         cudaFuncAttributeMaxDynamicSharedMemorySize, smemP);
    policy_kernel<<<LSEQ / 8, 256, smemP>>>(fn1_W, fn1_b, fn2_W, fn2_b,
                                            mu_W, mu_b, var_W, var_b, eps, out);
}